// round 8
// baseline (speedup 1.0000x reference)
#include <cuda_runtime.h>

// x: [8, 64, 64, 64, 64] fp32. Per (b,c) slice of 64^3:
//   s = sum over 2x2x2 windows of (max(window) + mean(window))
//   pooled[b,c] = s^2 ;  out[b,c] = pooled / max(||pooled[b,:]||_2, 1e-12)
//
// 4096 blocks x 64 threads = 512 slices x 8 chunks (128 KB each).
// 64 thr x 32 regs -> 28 blocks/SM resident (reg file 57K, 56 warps): one
// true wave, last-round imbalance down to 27-vs-28 chunks (~1%).
// Fused last-block finalize via atomic ticket.

#define CH 8
#define NBC 512
#define NBLK (NBC * CH)   // 4096

__device__ float g_partial[NBLK];
__device__ unsigned int g_counter = 0;

__global__ __launch_bounds__(64, 28) void fused_pool_kernel(const float* __restrict__ x,
                                                            float* __restrict__ out) {
    const int bc = blockIdx.x >> 3;
    const int q  = blockIdx.x & 7;     // chunk: h2 in [q*4, q*4+4)

    const int tid = threadIdx.x;       // 64 threads
    const int tx  = tid & 15;          // d-group: d = 4*tx..4*tx+3 (two d2 windows)
    const int g   = tid >> 4;          // 0..3: w2 start; strides w2 by 4

    // start: h2 = q*4, w2 = g, d = 4*tx
    const float* r0 = x + (size_t)bc * (64 * 64 * 64)
                        + ((size_t)(q * 8) * 4096) + (2 * g * 64) + (tx << 2);

    float acc = 0.0f;

    for (int h2i = 0; h2i < 4; h2i++) {           // 4 h2 rows in this chunk
        const float* r = r0;
        #pragma unroll
        for (int w2i = 0; w2i < 8; w2i++) {       // w2 = g + 4*w2i
            const float4 a = *(const float4*)(r);                 // (2h2,   2w2  )
            const float4 b = *(const float4*)(r + 64);            // (2h2,   2w2+1)
            const float4 c = *(const float4*)(r + 4096);          // (2h2+1, 2w2  )
            const float4 d = *(const float4*)(r + 4096 + 64);     // (2h2+1, 2w2+1)

            float m0 = fmaxf(fmaxf(fmaxf(a.x, a.y), fmaxf(b.x, b.y)),
                             fmaxf(fmaxf(c.x, c.y), fmaxf(d.x, d.y)));
            float m1 = fmaxf(fmaxf(fmaxf(a.z, a.w), fmaxf(b.z, b.w)),
                             fmaxf(fmaxf(c.z, c.w), fmaxf(d.z, d.w)));

            float sum = (a.x + a.y + a.z + a.w) + (b.x + b.y + b.z + b.w)
                      + (c.x + c.y + c.z + c.w) + (d.x + d.y + d.z + d.w);

            acc += m0 + m1 + sum * 0.125f;
            r += 2 * 4 * 64;                      // w2 += 4
        }
        r0 += 2 * 4096;                           // h2 += 1
    }

    // block reduce: warp shuffle then combine 2 warps via smem
    __shared__ float swarp[2];
    __shared__ int s_islast;
    #pragma unroll
    for (int off = 16; off > 0; off >>= 1)
        acc += __shfl_xor_sync(0xFFFFFFFFu, acc, off);
    if ((tid & 31) == 0) swarp[tid >> 5] = acc;
    __syncthreads();

    if (tid == 0) {
        g_partial[blockIdx.x] = swarp[0] + swarp[1];
        __threadfence();                          // publish before ticket
        unsigned int old = atomicAdd(&g_counter, 1u);
        s_islast = (old == (unsigned int)(gridDim.x - 1));
    }
    __syncthreads();
    if (!s_islast) return;

    // ---- last block: finalize (all 4096 partials visible) ----
    __threadfence();
    __shared__ float s_norm[8];

    // 64 threads: thread t -> batch b = t>>3, channels c8 = (t&7)*8 .. +7
    const int b  = tid >> 3;           // 0..7
    const int c8 = (tid & 7) << 3;     // 0,8,...,56

    float p[8], qsum = 0.0f;
    #pragma unroll
    for (int k = 0; k < 8; k++) {
        const int idx = ((b << 6) + c8 + k) * CH;
        float s = 0.0f;
        #pragma unroll
        for (int j = 0; j < CH; j++) s += g_partial[idx + j];
        p[k] = s * s;
        qsum += p[k] * p[k];
    }

    // reduce qsum over the 8 threads of the same batch (contiguous lanes)
    #pragma unroll
    for (int off = 4; off > 0; off >>= 1)
        qsum += __shfl_xor_sync(0xFFFFFFFFu, qsum, off);

    if ((tid & 7) == 0) s_norm[b] = fmaxf(sqrtf(qsum), 1e-12f);
    __syncthreads();

    const float inv = 1.0f / s_norm[b];
    #pragma unroll
    for (int k = 0; k < 8; k++)
        out[(b << 6) + c8 + k] = p[k] * inv;

    if (tid == 0) g_counter = 0;       // reset for next graph replay
}

extern "C" void kernel_launch(void* const* d_in, const int* in_sizes, int n_in,
                              void* d_out, int out_size) {
    const float* x = (const float*)d_in[0];
    float* out = (float*)d_out;
    fused_pool_kernel<<<NBLK, 64>>>(x, out);
}

// round 9
// speedup vs baseline: 1.0554x; 1.0554x over previous
#include <cuda_runtime.h>

// x: [8, 64, 64, 64, 64] fp32. Per (b,c) slice of 64^3:
//   s = sum over 2x2x2 windows of (max(window) + mean(window))
//   pooled[b,c] = s^2 ;  out[b,c] = pooled / max(||pooled[b,:]||_2, 1e-12)
//
// Perfectly balanced grid: 2072 blocks (= 148 SMs x 14) x 128 threads.
// Work = 16384 (bc,h2) row-pair units (32 KB each) split contiguously into
// 7-or-8-unit ranges -> every SM gets 110-111 units (<=1% imbalance) vs
// R7's 104-vs-112 (7.7%). Slice partials accumulate via atomicAdd into
// g_accum[512] (zero-init; finalize block resets it each run).

#define NBC 512
#define NBLK 2072
#define NUNITS 16384   // 512 slices * 32 h2 rows

__device__ float g_accum[NBC];          // zero at module load; re-zeroed by finalize
__device__ unsigned int g_counter = 0;

__global__ __launch_bounds__(128, 14) void fused_pool_kernel(const float* __restrict__ x,
                                                             float* __restrict__ out) {
    const int bid = blockIdx.x;
    const int tid = threadIdx.x;       // 128 threads
    const int tx  = tid & 15;          // d-group: d = 4*tx..4*tx+3 (two d2 windows)
    const int g   = tid >> 4;          // 0..7: w2 start; strided by 8

    // contiguous near-even split of 16384 units into 2072 ranges (7 or 8 each)
    // 16384/2072 = 2048/259
    int u  = (int)(((long long)bid * 2048) / 259);
    const int u1 = (int)(((long long)(bid + 1) * 2048) / 259);

    __shared__ float swarp[4];
    __shared__ int s_islast;

    while (u < u1) {                   // uniform across block
        const int bc   = u >> 5;
        const int uend = min(u1, (bc + 1) << 5);
        const float* sl = x + (size_t)bc * (64 * 64 * 64);

        float acc = 0.0f;
        for (; u < uend; u++) {
            const int h2 = u & 31;
            const float* r0 = sl + ((size_t)(2 * h2) * 4096) + (2 * g * 64) + (tx << 2);
            #pragma unroll
            for (int w2i = 0; w2i < 4; w2i++) {   // w2 = g + 8*w2i
                const float* r = r0 + w2i * 1024; // 2*8*64
                const float4 a = *(const float4*)(r);                 // (2h2,   2w2  )
                const float4 b = *(const float4*)(r + 64);            // (2h2,   2w2+1)
                const float4 c = *(const float4*)(r + 4096);          // (2h2+1, 2w2  )
                const float4 d = *(const float4*)(r + 4096 + 64);     // (2h2+1, 2w2+1)

                float m0 = fmaxf(fmaxf(fmaxf(a.x, a.y), fmaxf(b.x, b.y)),
                                 fmaxf(fmaxf(c.x, c.y), fmaxf(d.x, d.y)));
                float m1 = fmaxf(fmaxf(fmaxf(a.z, a.w), fmaxf(b.z, b.w)),
                                 fmaxf(fmaxf(c.z, c.w), fmaxf(d.z, d.w)));

                float sum = (a.x + a.y + a.z + a.w) + (b.x + b.y + b.z + b.w)
                          + (c.x + c.y + c.z + c.w) + (d.x + d.y + d.z + d.w);

                acc += m0 + m1 + sum * 0.125f;
            }
        }

        // block reduce this slice-segment, then atomicAdd into g_accum[bc]
        #pragma unroll
        for (int off = 16; off > 0; off >>= 1)
            acc += __shfl_xor_sync(0xFFFFFFFFu, acc, off);
        if ((tid & 31) == 0) swarp[tid >> 5] = acc;
        __syncthreads();
        if (tid == 0)
            atomicAdd(&g_accum[bc], swarp[0] + swarp[1] + swarp[2] + swarp[3]);
        __syncthreads();               // protect swarp reuse next segment
    }

    if (tid == 0) {
        __threadfence();               // publish atomics before ticket
        unsigned int old = atomicAdd(&g_counter, 1u);
        s_islast = (old == (unsigned int)(gridDim.x - 1));
    }
    __syncthreads();
    if (!s_islast) return;

    // ---- last block: finalize (all 512 accumulated sums visible) ----
    __threadfence();
    __shared__ float s_norm[8];

    const int b  = tid >> 4;           // 0..7
    const int c4 = (tid & 15) << 2;    // 0,4,...,60

    float p[4], qsum = 0.0f;
    #pragma unroll
    for (int k = 0; k < 4; k++) {
        const float s = g_accum[(b << 6) + c4 + k];
        p[k] = s * s;
        qsum += p[k] * p[k];
    }

    #pragma unroll
    for (int off = 8; off > 0; off >>= 1)
        qsum += __shfl_xor_sync(0xFFFFFFFFu, qsum, off);

    if ((tid & 15) == 0) s_norm[b] = fmaxf(sqrtf(qsum), 1e-12f);
    __syncthreads();

    const float inv = 1.0f / s_norm[b];
    #pragma unroll
    for (int k = 0; k < 4; k++)
        out[(b << 6) + c4 + k] = p[k] * inv;

    // reset accumulators + ticket for the next graph replay
    #pragma unroll
    for (int k = 0; k < 4; k++)
        g_accum[(b << 6) + c4 + k] = 0.0f;
    if (tid == 0) g_counter = 0;
}

extern "C" void kernel_launch(void* const* d_in, const int* in_sizes, int n_in,
                              void* d_out, int out_size) {
    const float* x = (const float*)d_in[0];
    float* out = (float*)d_out;
    fused_pool_kernel<<<NBLK, 128>>>(x, out);
}